// round 1
// baseline (speedup 1.0000x reference)
#include <cuda_runtime.h>
#include <cstdint>

#define Bq    32
#define CINq  32
#define COUTq 32
#define Hq    128
#define Wq    128
#define M1q   16
#define M2q   16
#define NMODE 32   // 2*M1

// Scratch: [kxi][ky][b][c] complex, 32*16*1024 float2 = 4 MB each
__device__ float2 g_Xf[NMODE * M2q * Bq * CINq];
__device__ float2 g_Yf[NMODE * M2q * Bq * COUTq];

__device__ __forceinline__ float2 cmul(float2 a, float2 b) {
    return make_float2(fmaf(a.x, b.x, -a.y * b.y), fmaf(a.x, b.y, a.y * b.x));
}

// ---------------------------------------------------------------------------
// Kernel 1: per (b, cin) tile. x[128][128] -> Xw[128][16] (DFT over W, 16 modes)
//           -> Xf[32 modes][16] (DFT over H, modes 0..15 and 112..127)
// grid = 1024, block = 256. Dynamic smem: x tile (padded) + Xw.
// ---------------------------------------------------------------------------
extern __shared__ float s_fwd[];
__global__ void __launch_bounds__(256) fno_fwd_kernel(const float* __restrict__ x) {
    float*  xs = s_fwd;                           // [128][129] padded
    float2* xw = (float2*)(s_fwd + 128 * 129);    // [h][ky] 128x16

    const int bi  = blockIdx.x;                   // b*32 + cin
    const int tid = threadIdx.x;
    const float* xp = x + (size_t)bi * (Hq * Wq);

    // coalesced load of the 128x128 tile into padded smem
    for (int idx = tid; idx < Hq * Wq; idx += 256) {
        int h = idx >> 7, w = idx & 127;
        xs[h * 129 + w] = xp[idx];
    }
    __syncthreads();

    const int ky = tid & 15;      // 0..15
    const int hb = tid >> 4;      // 0..15

    // Stage A: Xw[h][ky] = sum_w x[h][w] * e^{-2pi i ky w / 128}
    {
        float ss, cc;
        sincospif(-(float)ky / 64.0f, &ss, &cc);
        const float2 step = make_float2(cc, ss);
        float2 tw = make_float2(1.0f, 0.0f);
        float2 acc[8];
        #pragma unroll
        for (int j = 0; j < 8; j++) acc[j] = make_float2(0.f, 0.f);
        for (int w = 0; w < Wq; w++) {
            #pragma unroll
            for (int j = 0; j < 8; j++) {
                float xv = xs[(hb + 16 * j) * 129 + w];
                acc[j].x = fmaf(xv, tw.x, acc[j].x);
                acc[j].y = fmaf(xv, tw.y, acc[j].y);
            }
            tw = cmul(tw, step);
        }
        #pragma unroll
        for (int j = 0; j < 8; j++) xw[(hb + 16 * j) * 16 + ky] = acc[j];
    }
    __syncthreads();

    // Stage B: Xf[kxi][ky] = sum_h Xw[h][ky] * e^{-2pi i kx h / 128}
    // Thread handles kxi = kxg (kx = kxg) and kxi = kxg + 16 (kx = kxg + 112).
    {
        const int kxg = hb;       // 0..15
        float s1, c1, s2, c2;
        sincospif(-(float)kxg / 64.0f, &s1, &c1);            // e^{-2pi i kxg/128}
        sincospif(-(float)(kxg + 112) / 64.0f, &s2, &c2);    // e^{-2pi i (kxg+112)/128}
        const float2 st1 = make_float2(c1, s1);
        const float2 st2 = make_float2(c2, s2);
        float2 t1 = make_float2(1.f, 0.f), t2 = make_float2(1.f, 0.f);
        float2 a1 = make_float2(0.f, 0.f), a2 = make_float2(0.f, 0.f);
        for (int h = 0; h < Hq; h++) {
            float2 v = xw[h * 16 + ky];
            a1.x = fmaf(v.x, t1.x, a1.x); a1.x = fmaf(-v.y, t1.y, a1.x);
            a1.y = fmaf(v.x, t1.y, a1.y); a1.y = fmaf( v.y, t1.x, a1.y);
            a2.x = fmaf(v.x, t2.x, a2.x); a2.x = fmaf(-v.y, t2.y, a2.x);
            a2.y = fmaf(v.x, t2.y, a2.y); a2.y = fmaf( v.y, t2.x, a2.y);
            t1 = cmul(t1, st1);
            t2 = cmul(t2, st2);
        }
        g_Xf[((kxg)      * 16 + ky) * 1024 + bi] = a1;
        g_Xf[((kxg + 16) * 16 + ky) * 1024 + bi] = a2;
    }
}

// ---------------------------------------------------------------------------
// Kernel 2: spectral mix. One block per frequency (kxi, ky): 512 blocks.
//   Yf[f][b][o] = sum_i Xf[f][b][i] * W[i][o][kxi][ky]   (complex)
// ---------------------------------------------------------------------------
__global__ void __launch_bounds__(256) fno_mix_kernel(const float* __restrict__ wr,
                                                      const float* __restrict__ wi) {
    __shared__ float2 Xs[Bq * CINq];     // [b][i]
    __shared__ float2 Ws[CINq * COUTq];  // [i][o]
    const int f   = blockIdx.x;          // kxi*16 + ky
    const int kxi = f >> 4, ky = f & 15;
    const int tid = threadIdx.x;

    for (int idx = tid; idx < 1024; idx += 256) {
        Xs[idx] = g_Xf[f * 1024 + idx];
        int i = idx >> 5, o = idx & 31;
        int widx = ((i * COUTq + o) * NMODE + kxi) * M2q + ky;
        Ws[idx] = make_float2(wr[widx], wi[widx]);
    }
    __syncthreads();

    const int o  = tid & 31;
    const int bg = tid >> 5;   // 0..7
    #pragma unroll
    for (int j = 0; j < 4; j++) {
        int b = bg + 8 * j;
        float2 acc = make_float2(0.f, 0.f);
        #pragma unroll 8
        for (int i = 0; i < CINq; i++) {
            float2 xv = Xs[b * 32 + i];
            float2 wv = Ws[i * 32 + o];
            acc.x = fmaf(xv.x, wv.x, acc.x); acc.x = fmaf(-xv.y, wv.y, acc.x);
            acc.y = fmaf(xv.x, wv.y, acc.y); acc.y = fmaf( xv.y, wv.x, acc.y);
        }
        g_Yf[f * 1024 + b * 32 + o] = acc;
    }
}

// ---------------------------------------------------------------------------
// Kernel 3: per (b, cout) tile. Yf[32][16] -> y1[128][16] (inverse DFT over H)
//           -> out[128][128] (hermitian inverse DFT over W), scaled 1/(H*W).
// grid = 1024, block = 256.
// ---------------------------------------------------------------------------
__global__ void __launch_bounds__(256) fno_inv_kernel(float* __restrict__ out) {
    __shared__ float2 Ys[NMODE * M2q];   // [kxi][ky]
    __shared__ float2 y1[Hq * M2q];      // [h][ky]
    const int bo  = blockIdx.x;          // b*32 + o
    const int tid = threadIdx.x;

    for (int idx = tid; idx < NMODE * M2q; idx += 256)
        Ys[idx] = g_Yf[idx * 1024 + bo];
    __syncthreads();

    // y1[h][ky] = sum_kxi Ys[kxi][ky] * e^{+2pi i kx h / 128}
    {
        const int ky = tid & 15;
        const int hb = tid >> 4;
        #pragma unroll
        for (int j = 0; j < 8; j++) {
            int h = hb + 16 * j;
            float ss, cc;
            sincospif((float)h / 64.0f, &ss, &cc);
            const float2 stP = make_float2(cc,  ss);   // e^{+2pi i h/128}
            const float2 stN = make_float2(cc, -ss);   // e^{-2pi i h/128}
            float2 acc = make_float2(0.f, 0.f);
            float2 tw = make_float2(1.f, 0.f);
            #pragma unroll
            for (int k = 0; k < 16; k++) {             // kx = 0..15
                float2 v = Ys[k * 16 + ky];
                acc.x = fmaf(v.x, tw.x, acc.x); acc.x = fmaf(-v.y, tw.y, acc.x);
                acc.y = fmaf(v.x, tw.y, acc.y); acc.y = fmaf( v.y, tw.x, acc.y);
                tw = cmul(tw, stP);
            }
            tw = stN;                                  // kx = -1 (kxi = 31)
            #pragma unroll
            for (int k = 31; k >= 16; k--) {           // kx = -1..-16
                float2 v = Ys[k * 16 + ky];
                acc.x = fmaf(v.x, tw.x, acc.x); acc.x = fmaf(-v.y, tw.y, acc.x);
                acc.y = fmaf(v.x, tw.y, acc.y); acc.y = fmaf( v.y, tw.x, acc.y);
                tw = cmul(tw, stN);
            }
            y1[h * 16 + ky] = acc;
        }
    }
    __syncthreads();

    // out[h][w] = (1/16384) * ( Re y1[h][0] + 2*sum_{k=1}^{15} Re(y1[h][k] e^{2pi i k w/128}) )
    {
        const float scale = 1.0f / 16384.0f;
        const int w  = tid & 127;          // fixed per thread
        const int h0 = tid >> 7;           // 0 or 1
        float ss, cc;
        sincospif((float)w / 64.0f, &ss, &cc);
        const float2 step = make_float2(cc, ss);
        float* op = out + (size_t)bo * (Hq * Wq);
        #pragma unroll 4
        for (int j = 0; j < 64; j++) {
            int h = h0 + 2 * j;
            float2 tw = step;
            float v = y1[h * 16].x;
            #pragma unroll
            for (int k = 1; k < 16; k++) {
                float2 Y = y1[h * 16 + k];
                v = fmaf(2.0f * Y.x, tw.x, v);
                v = fmaf(-2.0f * Y.y, tw.y, v);
                tw = cmul(tw, step);
            }
            op[h * 128 + w] = v * scale;
        }
    }
}

// ---------------------------------------------------------------------------
extern "C" void kernel_launch(void* const* d_in, const int* in_sizes, int n_in,
                              void* d_out, int out_size) {
    const float* x  = (const float*)d_in[0];
    const float* wr = (const float*)d_in[1];
    const float* wi = (const float*)d_in[2];
    float* out = (float*)d_out;

    static bool attr_set = false;
    const int smem_fwd = 128 * 129 * 4 + 128 * 16 * 8;   // 82432 bytes
    if (!attr_set) {
        cudaFuncSetAttribute(fno_fwd_kernel,
                             cudaFuncAttributeMaxDynamicSharedMemorySize, smem_fwd);
        attr_set = true;
    }

    fno_fwd_kernel<<<Bq * CINq, 256, smem_fwd>>>(x);
    fno_mix_kernel<<<NMODE * M2q, 256>>>(wr, wi);
    fno_inv_kernel<<<Bq * COUTq, 256>>>(out);
}

// round 2
// speedup vs baseline: 1.4040x; 1.4040x over previous
#include <cuda_runtime.h>

// Problem constants: B=32, CIN=COUT=32, H=W=128, M1=M2=16, NMODE=2*M1=32.

// Global scratch (static __device__ arrays; no allocations).
__device__ float2 g_Xw[1024 * 16 * 128];  // [bc][ky][h]   16 MB
__device__ float2 g_Xf[512 * 1024];       // [f=kxi*16+ky][bc]  4 MB
__device__ float2 g_Yf[512 * 1024];       // [f][bo]            4 MB

__device__ __forceinline__ float2 cmul(float2 a, float2 b) {
    return make_float2(fmaf(a.x, b.x, -a.y * b.y), fmaf(a.x, b.y, a.y * b.x));
}
// a * conj(b)
__device__ __forceinline__ float2 cmulc(float2 a, float2 b) {
    return make_float2(fmaf(a.x, b.x, a.y * b.y), fmaf(a.y, b.x, -a.x * b.y));
}

// ---------------------------------------------------------------------------
// K1: W-DFT.  For each (b,c) and each h: Xw[ky] = sum_w x[h][w] e^{-2pi i ky w/128}
// grid = 2048 (tile bc x half), block = 256 = 16 ky x 16 hb. Each thread: 4 h rows.
// x streamed straight from gmem as float4 (rows are L1-broadcast across 16 ky).
// ---------------------------------------------------------------------------
__global__ void __launch_bounds__(256, 4) k1_wdft(const float* __restrict__ x) {
    const int bc   = blockIdx.x >> 1;
    const int half = blockIdx.x & 1;
    const int tid  = threadIdx.x;
    const int ky   = tid & 15;
    const int hb   = tid >> 4;

    const int h0 = half * 64 + hb;                 // rows h0 + 16j, j<4
    const float4* p0 = (const float4*)x + (size_t)bc * 4096 + h0 * 32;
    const float4* p1 = p0 + 512;                   // +16 rows
    const float4* p2 = p0 + 1024;
    const float4* p3 = p0 + 1536;

    float2 tw0, tw1, tw2, tw3, s4;
    {
        float s, c;
        tw0 = make_float2(1.f, 0.f);
        sincospif(-(float)ky        / 64.f, &s, &c); tw1 = make_float2(c, s);
        sincospif(-(float)(2 * ky)  / 64.f, &s, &c); tw2 = make_float2(c, s);
        sincospif(-(float)(3 * ky)  / 64.f, &s, &c); tw3 = make_float2(c, s);
        sincospif(-(float)(4 * ky)  / 64.f, &s, &c); s4  = make_float2(c, s);
    }
    float2 a0 = {0.f, 0.f}, a1 = {0.f, 0.f}, a2 = {0.f, 0.f}, a3 = {0.f, 0.f};

#define K1_ACC(TW, C)                                   \
    a0.x = fmaf(v0.C, TW.x, a0.x); a0.y = fmaf(v0.C, TW.y, a0.y); \
    a1.x = fmaf(v1.C, TW.x, a1.x); a1.y = fmaf(v1.C, TW.y, a1.y); \
    a2.x = fmaf(v2.C, TW.x, a2.x); a2.y = fmaf(v2.C, TW.y, a2.y); \
    a3.x = fmaf(v3.C, TW.x, a3.x); a3.y = fmaf(v3.C, TW.y, a3.y);

    #pragma unroll 2
    for (int w4 = 0; w4 < 32; w4++) {
        float4 v0 = p0[w4], v1 = p1[w4], v2 = p2[w4], v3 = p3[w4];
        K1_ACC(tw0, x) K1_ACC(tw1, y) K1_ACC(tw2, z) K1_ACC(tw3, w)
        tw0 = cmul(tw0, s4);
        tw1 = cmul(tw1, s4);
        tw2 = cmul(tw2, s4);
        tw3 = cmul(tw3, s4);
    }
#undef K1_ACC

    float2* o = g_Xw + ((size_t)bc * 16 + ky) * 128 + h0;
    o[0] = a0; o[16] = a1; o[32] = a2; o[48] = a3;
}

// ---------------------------------------------------------------------------
// K2: H-DFT.  Xf[kxi][ky] = sum_h Xw[ky][h] e^{-2pi i kx h/128},
// kx = kxi (kxi<16) or kxi+96 (kxi>=16).
// grid = 1024 (bc), block = 256 = 32 kxi x 8 ky2 (each thread: ky2, ky2+8).
// ---------------------------------------------------------------------------
__global__ void __launch_bounds__(256, 8) k2_hdft() {
    __shared__ float2 xw[16][130];    // padded rows to dodge bank conflicts
    const int bc  = blockIdx.x;
    const int tid = threadIdx.x;

    const float2* src = g_Xw + (size_t)bc * 2048;
    for (int idx = tid; idx < 2048; idx += 256) {
        xw[idx >> 7][idx & 127] = src[idx];
    }
    __syncthreads();

    const int ky2 = tid & 7;
    const int kxi = tid >> 3;
    const int kx  = (kxi < 16) ? kxi : (kxi + 96);

    float s, c;
    sincospif(-(float)kx / 64.f, &s, &c);
    const float2 st = make_float2(c, s);
    float2 t  = make_float2(1.f, 0.f);
    float2 aA = {0.f, 0.f}, aB = {0.f, 0.f};

    #pragma unroll 4
    for (int h = 0; h < 128; h++) {
        float2 vA = xw[ky2][h];
        float2 vB = xw[ky2 + 8][h];
        aA.x = fmaf(vA.x, t.x, aA.x); aA.x = fmaf(-vA.y, t.y, aA.x);
        aA.y = fmaf(vA.x, t.y, aA.y); aA.y = fmaf( vA.y, t.x, aA.y);
        aB.x = fmaf(vB.x, t.x, aB.x); aB.x = fmaf(-vB.y, t.y, aB.x);
        aB.y = fmaf(vB.x, t.y, aB.y); aB.y = fmaf( vB.y, t.x, aB.y);
        t = cmul(t, st);
    }

    g_Xf[((size_t)kxi * 16 + ky2)     * 1024 + bc] = aA;
    g_Xf[((size_t)kxi * 16 + ky2 + 8) * 1024 + bc] = aB;
}

// ---------------------------------------------------------------------------
// K3: spectral mix per frequency.  Yf[f][b][o] = sum_i Xf[f][b][i] * W[i][o][f]
// grid = 512, block = 256 = 32 o x 8 bg (each thread: 4 b).
// ---------------------------------------------------------------------------
__global__ void __launch_bounds__(256, 8) k3_mix(const float* __restrict__ wr,
                                                 const float* __restrict__ wi) {
    __shared__ float2 Xs[1024];      // [b][i]
    __shared__ float2 Ws[1024];      // [i][o]
    const int f   = blockIdx.x;
    const int kxi = f >> 4, kyy = f & 15;
    const int tid = threadIdx.x;

    for (int idx = tid; idx < 1024; idx += 256) {
        Xs[idx] = g_Xf[(size_t)f * 1024 + idx];
        int i = idx >> 5, o = idx & 31;
        int widx = ((i * 32 + o) * 32 + kxi) * 16 + kyy;
        Ws[idx] = make_float2(wr[widx], wi[widx]);
    }
    __syncthreads();

    const int o  = tid & 31;
    const int bg = tid >> 5;
    float2 a[4];
    #pragma unroll
    for (int j = 0; j < 4; j++) a[j] = make_float2(0.f, 0.f);

    #pragma unroll 4
    for (int i = 0; i < 32; i++) {
        float2 wv = Ws[i * 32 + o];
        #pragma unroll
        for (int j = 0; j < 4; j++) {
            float2 xv = Xs[(bg + 8 * j) * 32 + i];
            a[j].x = fmaf(xv.x, wv.x, a[j].x); a[j].x = fmaf(-xv.y, wv.y, a[j].x);
            a[j].y = fmaf(xv.x, wv.y, a[j].y); a[j].y = fmaf( xv.y, wv.x, a[j].y);
        }
    }
    #pragma unroll
    for (int j = 0; j < 4; j++)
        g_Yf[(size_t)f * 1024 + (bg + 8 * j) * 32 + o] = a[j];
}

// ---------------------------------------------------------------------------
// K4: inverse.  Stage 1: y1[h][ky] = sum_kxi Yf[kxi][ky] e^{+2pi i kx h/128}.
// Stage 2: out[h][w] = (1/16384)(y1[h][0].re + 2 sum_{k=1..15} Re(y1[h][k] e^{2pi i k w/128}))
// grid = 1024 (bo), block = 256.
// ---------------------------------------------------------------------------
__global__ void __launch_bounds__(256, 3) k4_inv(float* __restrict__ out) {
    __shared__ float2 Ys[512];       // [kxi][ky]
    __shared__ float2 y1[2048];      // [h][ky]
    const int bo  = blockIdx.x;
    const int tid = threadIdx.x;

    for (int idx = tid; idx < 512; idx += 256)
        Ys[idx] = g_Yf[(size_t)idx * 1024 + bo];
    __syncthreads();

    // Stage 1: thread (ky, hb) owns h = hb + 16j, j<8. Ys value loaded once per kx,
    // 8 twiddle chains advanced in lockstep.
    {
        const int ky = tid & 15;
        const int hb = tid >> 4;
        float2 stp[8], tw[8], acc[8];
        #pragma unroll
        for (int j = 0; j < 8; j++) {
            float s, c;
            sincospif((float)(hb + 16 * j) / 64.f, &s, &c);
            stp[j] = make_float2(c, s);
            tw[j]  = make_float2(1.f, 0.f);
            acc[j] = make_float2(0.f, 0.f);
        }
        #pragma unroll 2
        for (int k = 0; k < 16; k++) {          // kx = 0..15
            float2 v = Ys[k * 16 + ky];
            #pragma unroll
            for (int j = 0; j < 8; j++) {
                acc[j].x = fmaf(v.x, tw[j].x, acc[j].x); acc[j].x = fmaf(-v.y, tw[j].y, acc[j].x);
                acc[j].y = fmaf(v.x, tw[j].y, acc[j].y); acc[j].y = fmaf( v.y, tw[j].x, acc[j].y);
                tw[j] = cmul(tw[j], stp[j]);
            }
        }
        #pragma unroll
        for (int j = 0; j < 8; j++) tw[j] = make_float2(stp[j].x, -stp[j].y);
        #pragma unroll 2
        for (int k = 31; k >= 16; k--) {        // kx = -1..-16
            float2 v = Ys[k * 16 + ky];
            #pragma unroll
            for (int j = 0; j < 8; j++) {
                acc[j].x = fmaf(v.x, tw[j].x, acc[j].x); acc[j].x = fmaf(-v.y, tw[j].y, acc[j].x);
                acc[j].y = fmaf(v.x, tw[j].y, acc[j].y); acc[j].y = fmaf( v.y, tw[j].x, acc[j].y);
                tw[j] = cmulc(tw[j], stp[j]);
            }
        }
        #pragma unroll
        for (int j = 0; j < 8; j++) y1[(hb + 16 * j) * 16 + ky] = acc[j];
    }
    __syncthreads();

    // Stage 2: thread (w, h0) with hoisted twiddle registers (computed once, exact).
    {
        const float inv = 1.0f / 16384.0f;
        const int w  = tid & 127;
        const int h0 = tid >> 7;
        float twr[15], twi[15];
        #pragma unroll
        for (int k = 1; k < 16; k++) {
            float s, c;
            sincospif((float)(k * w) / 64.f, &s, &c);
            twr[k - 1] = c * (2.0f * inv);
            twi[k - 1] = s * (2.0f * inv);
        }
        float* op = out + (size_t)bo * 16384;
        #pragma unroll 2
        for (int j = 0; j < 64; j++) {
            int h = h0 + 2 * j;
            const float4* r = (const float4*)(y1 + h * 16);
            float4 r0 = r[0];
            float v = r0.x * inv;
            v = fmaf(r0.z, twr[0], v); v = fmaf(-r0.w, twi[0], v);
            #pragma unroll
            for (int m = 1; m < 8; m++) {
                float4 rm = r[m];
                v = fmaf(rm.x, twr[2 * m - 1], v); v = fmaf(-rm.y, twi[2 * m - 1], v);
                v = fmaf(rm.z, twr[2 * m],     v); v = fmaf(-rm.w, twi[2 * m],     v);
            }
            op[h * 128 + w] = v;
        }
    }
}

// ---------------------------------------------------------------------------
extern "C" void kernel_launch(void* const* d_in, const int* in_sizes, int n_in,
                              void* d_out, int out_size) {
    const float* x  = (const float*)d_in[0];
    const float* wr = (const float*)d_in[1];
    const float* wi = (const float*)d_in[2];
    float* out = (float*)d_out;

    k1_wdft<<<2048, 256>>>(x);
    k2_hdft<<<1024, 256>>>();
    k3_mix<<<512, 256>>>(wr, wi);
    k4_inv<<<1024, 256>>>(out);
}

// round 3
// speedup vs baseline: 1.4172x; 1.0094x over previous
#include <cuda_runtime.h>

// Problem constants: B=32, CIN=COUT=32, H=W=128, M1=M2=16, NMODE=2*M1=32.

// Global scratch (static __device__ arrays; no allocations).
__device__ float2 g_Xw[1024 * 16 * 128];  // [bc][ky][h]   16 MB
__device__ float2 g_Xf[512 * 1024];       // [f=kxi*16+ky][bc]  4 MB
__device__ float2 g_Yf[512 * 1024];       // [f][bo]            4 MB

__device__ __forceinline__ float2 cmul(float2 a, float2 b) {
    return make_float2(fmaf(a.x, b.x, -a.y * b.y), fmaf(a.x, b.y, a.y * b.x));
}
// a * conj(b)
__device__ __forceinline__ float2 cmulc(float2 a, float2 b) {
    return make_float2(fmaf(a.x, b.x, a.y * b.y), fmaf(a.y, b.x, -a.x * b.y));
}

// ---------------------------------------------------------------------------
// K1: W-DFT.  For each (b,c) and each h: Xw[ky] = sum_w x[h][w] e^{-2pi i ky w/128}
// grid = 2048 (tile bc x half), block = 256 = 16 ky x 16 hb. Each thread: 4 h rows.
// x streamed straight from gmem as float4 (rows are L1-broadcast across 16 ky).
// ---------------------------------------------------------------------------
__global__ void __launch_bounds__(256, 4) k1_wdft(const float* __restrict__ x) {
    const int bc   = blockIdx.x >> 1;
    const int half = blockIdx.x & 1;
    const int tid  = threadIdx.x;
    const int ky   = tid & 15;
    const int hb   = tid >> 4;

    const int h0 = half * 64 + hb;                 // rows h0 + 16j, j<4
    const float4* p0 = (const float4*)x + (size_t)bc * 4096 + h0 * 32;
    const float4* p1 = p0 + 512;                   // +16 rows
    const float4* p2 = p0 + 1024;
    const float4* p3 = p0 + 1536;

    float2 tw0, tw1, tw2, tw3, s4;
    {
        float s, c;
        tw0 = make_float2(1.f, 0.f);
        sincospif(-(float)ky        / 64.f, &s, &c); tw1 = make_float2(c, s);
        sincospif(-(float)(2 * ky)  / 64.f, &s, &c); tw2 = make_float2(c, s);
        sincospif(-(float)(3 * ky)  / 64.f, &s, &c); tw3 = make_float2(c, s);
        sincospif(-(float)(4 * ky)  / 64.f, &s, &c); s4  = make_float2(c, s);
    }
    float2 a0 = {0.f, 0.f}, a1 = {0.f, 0.f}, a2 = {0.f, 0.f}, a3 = {0.f, 0.f};

#define K1_ACC(TW, C)                                   \
    a0.x = fmaf(v0.C, TW.x, a0.x); a0.y = fmaf(v0.C, TW.y, a0.y); \
    a1.x = fmaf(v1.C, TW.x, a1.x); a1.y = fmaf(v1.C, TW.y, a1.y); \
    a2.x = fmaf(v2.C, TW.x, a2.x); a2.y = fmaf(v2.C, TW.y, a2.y); \
    a3.x = fmaf(v3.C, TW.x, a3.x); a3.y = fmaf(v3.C, TW.y, a3.y);

    #pragma unroll 2
    for (int w4 = 0; w4 < 32; w4++) {
        float4 v0 = p0[w4], v1 = p1[w4], v2 = p2[w4], v3 = p3[w4];
        K1_ACC(tw0, x) K1_ACC(tw1, y) K1_ACC(tw2, z) K1_ACC(tw3, w)
        tw0 = cmul(tw0, s4);
        tw1 = cmul(tw1, s4);
        tw2 = cmul(tw2, s4);
        tw3 = cmul(tw3, s4);
    }
#undef K1_ACC

    float2* o = g_Xw + ((size_t)bc * 16 + ky) * 128 + h0;
    o[0] = a0; o[16] = a1; o[32] = a2; o[48] = a3;
}

// ---------------------------------------------------------------------------
// K2: H-DFT.  Xf[kxi][ky] = sum_h Xw[ky][h] e^{-2pi i kx h/128},
// kx = kxi (kxi<16) or kxi+96 (kxi>=16).
// grid = 1024 (bc), block = 256 = 32 kxi x 8 ky2 (each thread: ky2, ky2+8).
// ---------------------------------------------------------------------------
__global__ void __launch_bounds__(256, 8) k2_hdft() {
    __shared__ float2 xw[16][130];    // padded rows to dodge bank conflicts
    const int bc  = blockIdx.x;
    const int tid = threadIdx.x;

    const float2* src = g_Xw + (size_t)bc * 2048;
    for (int idx = tid; idx < 2048; idx += 256) {
        xw[idx >> 7][idx & 127] = src[idx];
    }
    __syncthreads();

    const int ky2 = tid & 7;
    const int kxi = tid >> 3;
    const int kx  = (kxi < 16) ? kxi : (kxi + 96);

    float s, c;
    sincospif(-(float)kx / 64.f, &s, &c);
    const float2 st = make_float2(c, s);
    float2 t  = make_float2(1.f, 0.f);
    float2 aA = {0.f, 0.f}, aB = {0.f, 0.f};

    #pragma unroll 4
    for (int h = 0; h < 128; h++) {
        float2 vA = xw[ky2][h];
        float2 vB = xw[ky2 + 8][h];
        aA.x = fmaf(vA.x, t.x, aA.x); aA.x = fmaf(-vA.y, t.y, aA.x);
        aA.y = fmaf(vA.x, t.y, aA.y); aA.y = fmaf( vA.y, t.x, aA.y);
        aB.x = fmaf(vB.x, t.x, aB.x); aB.x = fmaf(-vB.y, t.y, aB.x);
        aB.y = fmaf(vB.x, t.y, aB.y); aB.y = fmaf( vB.y, t.x, aB.y);
        t = cmul(t, st);
    }

    g_Xf[((size_t)kxi * 16 + ky2)     * 1024 + bc] = aA;
    g_Xf[((size_t)kxi * 16 + ky2 + 8) * 1024 + bc] = aB;
}

// ---------------------------------------------------------------------------
// K3: spectral mix per frequency.  Yf[f][b][o] = sum_i Xf[f][b][i] * W[i][o][f]
// grid = 512, block = 256 = 32 o x 8 bg (each thread: 4 b).
// ---------------------------------------------------------------------------
__global__ void __launch_bounds__(256, 8) k3_mix(const float* __restrict__ wr,
                                                 const float* __restrict__ wi) {
    __shared__ float2 Xs[1024];      // [b][i]
    __shared__ float2 Ws[1024];      // [i][o]
    const int f   = blockIdx.x;
    const int kxi = f >> 4, kyy = f & 15;
    const int tid = threadIdx.x;

    for (int idx = tid; idx < 1024; idx += 256) {
        Xs[idx] = g_Xf[(size_t)f * 1024 + idx];
        int i = idx >> 5, o = idx & 31;
        int widx = ((i * 32 + o) * 32 + kxi) * 16 + kyy;
        Ws[idx] = make_float2(wr[widx], wi[widx]);
    }
    __syncthreads();

    const int o  = tid & 31;
    const int bg = tid >> 5;
    float2 a[4];
    #pragma unroll
    for (int j = 0; j < 4; j++) a[j] = make_float2(0.f, 0.f);

    #pragma unroll 4
    for (int i = 0; i < 32; i++) {
        float2 wv = Ws[i * 32 + o];
        #pragma unroll
        for (int j = 0; j < 4; j++) {
            float2 xv = Xs[(bg + 8 * j) * 32 + i];
            a[j].x = fmaf(xv.x, wv.x, a[j].x); a[j].x = fmaf(-xv.y, wv.y, a[j].x);
            a[j].y = fmaf(xv.x, wv.y, a[j].y); a[j].y = fmaf( xv.y, wv.x, a[j].y);
        }
    }
    #pragma unroll
    for (int j = 0; j < 4; j++)
        g_Yf[(size_t)f * 1024 + (bg + 8 * j) * 32 + o] = a[j];
}

// ---------------------------------------------------------------------------
// K4: inverse.  Stage 1: y1[h][ky] = sum_kxi Yf[kxi][ky] e^{+2pi i kx h/128}.
// Stage 2: out[h][w] = (1/16384)(y1[h][0].re + 2 sum_{k=1..15} Re(y1[h][k] e^{2pi i k w/128}))
// grid = 1024 (bo), block = 256.
// ---------------------------------------------------------------------------
__global__ void __launch_bounds__(256, 3) k4_inv(float* __restrict__ out) {
    __shared__ float2 Ys[512];       // [kxi][ky]
    __shared__ float2 y1[2048];      // [h][ky]
    const int bo  = blockIdx.x;
    const int tid = threadIdx.x;

    for (int idx = tid; idx < 512; idx += 256)
        Ys[idx] = g_Yf[(size_t)idx * 1024 + bo];
    __syncthreads();

    // Stage 1: thread (ky, hb) owns h = hb + 16j, j<8. Ys value loaded once per kx,
    // 8 twiddle chains advanced in lockstep.
    {
        const int ky = tid & 15;
        const int hb = tid >> 4;
        float2 stp[8], tw[8], acc[8];
        #pragma unroll
        for (int j = 0; j < 8; j++) {
            float s, c;
            sincospif((float)(hb + 16 * j) / 64.f, &s, &c);
            stp[j] = make_float2(c, s);
            tw[j]  = make_float2(1.f, 0.f);
            acc[j] = make_float2(0.f, 0.f);
        }
        #pragma unroll 2
        for (int k = 0; k < 16; k++) {          // kx = 0..15
            float2 v = Ys[k * 16 + ky];
            #pragma unroll
            for (int j = 0; j < 8; j++) {
                acc[j].x = fmaf(v.x, tw[j].x, acc[j].x); acc[j].x = fmaf(-v.y, tw[j].y, acc[j].x);
                acc[j].y = fmaf(v.x, tw[j].y, acc[j].y); acc[j].y = fmaf( v.y, tw[j].x, acc[j].y);
                tw[j] = cmul(tw[j], stp[j]);
            }
        }
        #pragma unroll
        for (int j = 0; j < 8; j++) tw[j] = make_float2(stp[j].x, -stp[j].y);
        #pragma unroll 2
        for (int k = 31; k >= 16; k--) {        // kx = -1..-16
            float2 v = Ys[k * 16 + ky];
            #pragma unroll
            for (int j = 0; j < 8; j++) {
                acc[j].x = fmaf(v.x, tw[j].x, acc[j].x); acc[j].x = fmaf(-v.y, tw[j].y, acc[j].x);
                acc[j].y = fmaf(v.x, tw[j].y, acc[j].y); acc[j].y = fmaf( v.y, tw[j].x, acc[j].y);
                tw[j] = cmulc(tw[j], stp[j]);
            }
        }
        #pragma unroll
        for (int j = 0; j < 8; j++) y1[(hb + 16 * j) * 16 + ky] = acc[j];
    }
    __syncthreads();

    // Stage 2: thread (w, h0) with hoisted twiddle registers (computed once, exact).
    {
        const float inv = 1.0f / 16384.0f;
        const int w  = tid & 127;
        const int h0 = tid >> 7;
        float twr[15], twi[15];
        #pragma unroll
        for (int k = 1; k < 16; k++) {
            float s, c;
            sincospif((float)(k * w) / 64.f, &s, &c);
            twr[k - 1] = c * (2.0f * inv);
            twi[k - 1] = s * (2.0f * inv);
        }
        float* op = out + (size_t)bo * 16384;
        #pragma unroll 2
        for (int j = 0; j < 64; j++) {
            int h = h0 + 2 * j;
            const float4* r = (const float4*)(y1 + h * 16);
            float4 r0 = r[0];
            float v = r0.x * inv;
            v = fmaf(r0.z, twr[0], v); v = fmaf(-r0.w, twi[0], v);
            #pragma unroll
            for (int m = 1; m < 8; m++) {
                float4 rm = r[m];
                v = fmaf(rm.x, twr[2 * m - 1], v); v = fmaf(-rm.y, twi[2 * m - 1], v);
                v = fmaf(rm.z, twr[2 * m],     v); v = fmaf(-rm.w, twi[2 * m],     v);
            }
            op[h * 128 + w] = v;
        }
    }
}

// ---------------------------------------------------------------------------
extern "C" void kernel_launch(void* const* d_in, const int* in_sizes, int n_in,
                              void* d_out, int out_size) {
    const float* x  = (const float*)d_in[0];
    const float* wr = (const float*)d_in[1];
    const float* wi = (const float*)d_in[2];
    float* out = (float*)d_out;

    k1_wdft<<<2048, 256>>>(x);
    k2_hdft<<<1024, 256>>>();
    k3_mix<<<512, 256>>>(wr, wi);
    k4_inv<<<1024, 256>>>(out);
}